// round 9
// baseline (speedup 1.0000x reference)
#include <cuda_runtime.h>
#include <cuda_bf16.h>

// Skewed L1 loss mean reduction, single kernel.
// lam(y) with LIM=(0,1), MEDIAN=0.5, LMAX=1 simplifies to 2y-1 on both branches.
// term = |p - t| * exp(sign(t - p) * (2t - 1));  output = mean(term).
//
// Blocks atomicAdd their scaled partial into a __device__ accumulator as they
// finish (overlapped with still-running blocks). A ticket counter elects the
// last block, which drains the accumulator with atomicExch (read + reset in
// one op) and writes the scalar output. Self-resetting => graph-replay safe,
// and no separate zero kernel.

#define NBLOCKS (148 * 8)
#define NTHREADS 256

__device__ float g_accum = 0.0f;
__device__ unsigned int g_ticket = 0;

__global__ __launch_bounds__(NTHREADS) void skewed_loss_kernel(
    const float* __restrict__ y_pred,
    const float* __restrict__ y_true,
    float* __restrict__ out,
    int n4,          // number of float4 chunks
    float inv_n)
{
    const float4* p4 = reinterpret_cast<const float4*>(y_pred);
    const float4* t4 = reinterpret_cast<const float4*>(y_true);

    float acc = 0.0f;
    const int stride = NBLOCKS * NTHREADS;
    for (int i = blockIdx.x * NTHREADS + threadIdx.x; i < n4; i += stride) {
        float4 p = p4[i];
        float4 t = t4[i];

        {
            float d = p.x - t.x;
            float lam = 2.0f * t.x - 1.0f;
            float e = (d <= 0.0f) ? lam : -lam;
            acc += fabsf(d) * __expf(e);
        }
        {
            float d = p.y - t.y;
            float lam = 2.0f * t.y - 1.0f;
            float e = (d <= 0.0f) ? lam : -lam;
            acc += fabsf(d) * __expf(e);
        }
        {
            float d = p.z - t.z;
            float lam = 2.0f * t.z - 1.0f;
            float e = (d <= 0.0f) ? lam : -lam;
            acc += fabsf(d) * __expf(e);
        }
        {
            float d = p.w - t.w;
            float lam = 2.0f * t.w - 1.0f;
            float e = (d <= 0.0f) ? lam : -lam;
            acc += fabsf(d) * __expf(e);
        }
    }

    // Warp reduction
    #pragma unroll
    for (int off = 16; off > 0; off >>= 1)
        acc += __shfl_xor_sync(0xFFFFFFFF, acc, off);

    // Block reduction via shared
    __shared__ float warp_sums[NTHREADS / 32];
    int lane = threadIdx.x & 31;
    int wid  = threadIdx.x >> 5;
    if (lane == 0) warp_sums[wid] = acc;
    __syncthreads();

    if (threadIdx.x == 0) {
        float v = 0.0f;
        #pragma unroll
        for (int w = 0; w < NTHREADS / 32; w++)
            v += warp_sums[w];

        // Publish partial, then take a ticket.
        atomicAdd(&g_accum, v * inv_n);
        __threadfence();
        unsigned int ticket = atomicAdd(&g_ticket, 1u);

        if (ticket == NBLOCKS - 1) {
            // All other partials are visible (each was published before its
            // ticket increment, with a fence in between). Drain + reset.
            __threadfence();
            float total = atomicExch(&g_accum, 0.0f);
            out[0] = total;
            g_ticket = 0;   // reset for next graph replay
        }
    }
}

extern "C" void kernel_launch(void* const* d_in, const int* in_sizes, int n_in,
                              void* d_out, int out_size) {
    const float* y_pred = (const float*)d_in[0];
    const float* y_true = (const float*)d_in[1];
    float* out = (float*)d_out;

    int n = in_sizes[0];          // 33554432, divisible by 4
    int n4 = n >> 2;
    float inv_n = 1.0f / (float)n;

    skewed_loss_kernel<<<NBLOCKS, NTHREADS>>>(y_pred, y_true, out, n4, inv_n);
}

// round 11
// speedup vs baseline: 1.0071x; 1.0071x over previous
#include <cuda_runtime.h>
#include <cuda_bf16.h>

// Skewed L1 loss mean reduction, single kernel.
// lam(y) with LIM=(0,1), MEDIAN=0.5, LMAX=1 simplifies to 2y-1 on both branches.
// term = |p - t| * exp(sign(t - p) * (2t - 1));  output = mean(term).
//
// Mainloop unrolled x2: 4 LDG.128 batched at the loop head (MLP_p1=4) for a
// deeper L1tex queue, under __launch_bounds__(256,8) to pin regs <= 32 and
// keep 8 blocks/SM resident. Epilogue: blocks atomicAdd scaled partials into
// a __device__ accumulator as they finish; ticket counter elects the last
// block, which drains with atomicExch (read+reset in one op) and writes out.
// Self-resetting => graph-replay safe, no zero kernel, no serial tail.

#define NBLOCKS (148 * 8)
#define NTHREADS 256

__device__ float g_accum = 0.0f;
__device__ unsigned int g_ticket = 0;

__device__ __forceinline__ float skew_term(float p, float t) {
    float d = p - t;
    float lam = 2.0f * t - 1.0f;
    float e = (d <= 0.0f) ? lam : -lam;
    return fabsf(d) * __expf(e);
}

__global__ __launch_bounds__(NTHREADS, 8) void skewed_loss_kernel(
    const float* __restrict__ y_pred,
    const float* __restrict__ y_true,
    float* __restrict__ out,
    int n4,          // number of float4 chunks
    float inv_n)
{
    const float4* p4 = reinterpret_cast<const float4*>(y_pred);
    const float4* t4 = reinterpret_cast<const float4*>(y_true);

    float acc = 0.0f;
    const int stride = NBLOCKS * NTHREADS;
    int i = blockIdx.x * NTHREADS + threadIdx.x;

    // Unroll x2: 4 independent 128-bit loads issued back-to-back.
    for (; i + stride < n4; i += 2 * stride) {
        float4 p0 = p4[i];
        float4 t0 = t4[i];
        float4 p1 = p4[i + stride];
        float4 t1 = t4[i + stride];

        acc += skew_term(p0.x, t0.x);
        acc += skew_term(p0.y, t0.y);
        acc += skew_term(p0.z, t0.z);
        acc += skew_term(p0.w, t0.w);
        acc += skew_term(p1.x, t1.x);
        acc += skew_term(p1.y, t1.y);
        acc += skew_term(p1.z, t1.z);
        acc += skew_term(p1.w, t1.w);
    }
    if (i < n4) {
        float4 p = p4[i];
        float4 t = t4[i];
        acc += skew_term(p.x, t.x);
        acc += skew_term(p.y, t.y);
        acc += skew_term(p.z, t.z);
        acc += skew_term(p.w, t.w);
    }

    // Warp reduction
    #pragma unroll
    for (int off = 16; off > 0; off >>= 1)
        acc += __shfl_xor_sync(0xFFFFFFFF, acc, off);

    // Block reduction via shared
    __shared__ float warp_sums[NTHREADS / 32];
    int lane = threadIdx.x & 31;
    int wid  = threadIdx.x >> 5;
    if (lane == 0) warp_sums[wid] = acc;
    __syncthreads();

    if (threadIdx.x == 0) {
        float v = 0.0f;
        #pragma unroll
        for (int w = 0; w < NTHREADS / 32; w++)
            v += warp_sums[w];

        // Publish partial, then take a ticket.
        atomicAdd(&g_accum, v * inv_n);
        __threadfence();
        unsigned int ticket = atomicAdd(&g_ticket, 1u);

        if (ticket == NBLOCKS - 1) {
            // All partials visible (publish happened before each ticket, with
            // a fence between). Drain + reset in one atomic.
            __threadfence();
            float total = atomicExch(&g_accum, 0.0f);
            out[0] = total;
            g_ticket = 0;   // reset for next graph replay
        }
    }
}

extern "C" void kernel_launch(void* const* d_in, const int* in_sizes, int n_in,
                              void* d_out, int out_size) {
    const float* y_pred = (const float*)d_in[0];
    const float* y_true = (const float*)d_in[1];
    float* out = (float*)d_out;

    int n = in_sizes[0];          // 33554432, divisible by 4
    int n4 = n >> 2;
    float inv_n = 1.0f / (float)n;

    skewed_loss_kernel<<<NBLOCKS, NTHREADS>>>(y_pred, y_true, out, n4, inv_n);
}

// round 12
// speedup vs baseline: 1.0230x; 1.0158x over previous
#include <cuda_runtime.h>
#include <cuda_bf16.h>

// Skewed L1 loss mean reduction, single kernel.
// lam(y) with LIM=(0,1), MEDIAN=0.5, LMAX=1 simplifies to 2y-1 on both branches.
// term = |p - t| * exp(sign(t - p) * (2t - 1));  output = mean(term).
//
// Mainloop: R2's minimal form (measured fastest: 24 regs, 41.9us, DRAM 82%).
// Epilogue: blocks atomicAdd scaled partials into a __device__ accumulator as
// they finish (overlapped with running blocks); a ticket counter elects the
// last block, which drains with atomicExch (read + reset in one atomic) and
// writes the scalar. Self-resetting => graph-replay safe, no zero kernel,
// no serial end-of-kernel reduction tail.

#define NBLOCKS (148 * 8)
#define NTHREADS 256

__device__ float g_accum = 0.0f;
__device__ unsigned int g_ticket = 0;

__global__ __launch_bounds__(NTHREADS) void skewed_loss_kernel(
    const float* __restrict__ y_pred,
    const float* __restrict__ y_true,
    float* __restrict__ out,
    int n4,          // number of float4 chunks
    float inv_n)
{
    const float4* p4 = reinterpret_cast<const float4*>(y_pred);
    const float4* t4 = reinterpret_cast<const float4*>(y_true);

    float acc = 0.0f;
    const int stride = NBLOCKS * NTHREADS;
    for (int i = blockIdx.x * NTHREADS + threadIdx.x; i < n4; i += stride) {
        float4 p = p4[i];
        float4 t = t4[i];

        {
            float d = p.x - t.x;
            float lam = 2.0f * t.x - 1.0f;
            float e = (d <= 0.0f) ? lam : -lam;
            acc += fabsf(d) * __expf(e);
        }
        {
            float d = p.y - t.y;
            float lam = 2.0f * t.y - 1.0f;
            float e = (d <= 0.0f) ? lam : -lam;
            acc += fabsf(d) * __expf(e);
        }
        {
            float d = p.z - t.z;
            float lam = 2.0f * t.z - 1.0f;
            float e = (d <= 0.0f) ? lam : -lam;
            acc += fabsf(d) * __expf(e);
        }
        {
            float d = p.w - t.w;
            float lam = 2.0f * t.w - 1.0f;
            float e = (d <= 0.0f) ? lam : -lam;
            acc += fabsf(d) * __expf(e);
        }
    }

    // Warp reduction
    #pragma unroll
    for (int off = 16; off > 0; off >>= 1)
        acc += __shfl_xor_sync(0xFFFFFFFF, acc, off);

    // Block reduction via shared
    __shared__ float warp_sums[NTHREADS / 32];
    int lane = threadIdx.x & 31;
    int wid  = threadIdx.x >> 5;
    if (lane == 0) warp_sums[wid] = acc;
    __syncthreads();

    if (threadIdx.x == 0) {
        float v = 0.0f;
        #pragma unroll
        for (int w = 0; w < NTHREADS / 32; w++)
            v += warp_sums[w];

        // Publish partial (overlapped with other blocks' streaming), then
        // take a ticket.
        atomicAdd(&g_accum, v * inv_n);
        __threadfence();
        unsigned int ticket = atomicAdd(&g_ticket, 1u);

        if (ticket == NBLOCKS - 1) {
            // All partials visible (each published before its ticket, fenced).
            // Drain + reset in one atomic.
            __threadfence();
            float total = atomicExch(&g_accum, 0.0f);
            out[0] = total;
            g_ticket = 0;   // reset for next graph replay
        }
    }
}

extern "C" void kernel_launch(void* const* d_in, const int* in_sizes, int n_in,
                              void* d_out, int out_size) {
    const float* y_pred = (const float*)d_in[0];
    const float* y_true = (const float*)d_in[1];
    float* out = (float*)d_out;

    int n = in_sizes[0];          // 33554432, divisible by 4
    int n4 = n >> 2;
    float inv_n = 1.0f / (float)n;

    skewed_loss_kernel<<<NBLOCKS, NTHREADS>>>(y_pred, y_true, out, n4, inv_n);
}

// round 13
// speedup vs baseline: 1.0304x; 1.0072x over previous
#include <cuda_runtime.h>
#include <cuda_bf16.h>

// Skewed L1 loss mean reduction.
// lam(y) with LIM=(0,1), MEDIAN=0.5, LMAX=1 simplifies to 2y-1 on both branches.
// term = |p - t| * exp(sign(t - p) * (2t - 1));  output = mean(term).
//
// Configuration with best measured e2e (R2): minimal 24-reg mainloop, each
// block atomicAdds its scaled partial directly into out[0] (overlapped with
// other blocks still streaming -> no serial tail, no extra kernel state).
// out[0] is zeroed by a cudaMemsetAsync node (cheaper than a zero-kernel
// launch node, fully graph-capturable, no allocation).

#define NBLOCKS (148 * 8)
#define NTHREADS 256

__global__ __launch_bounds__(NTHREADS) void skewed_loss_kernel(
    const float* __restrict__ y_pred,
    const float* __restrict__ y_true,
    float* __restrict__ out,
    int n4,          // number of float4 chunks
    float inv_n)
{
    const float4* p4 = reinterpret_cast<const float4*>(y_pred);
    const float4* t4 = reinterpret_cast<const float4*>(y_true);

    float acc = 0.0f;
    const int stride = NBLOCKS * NTHREADS;
    for (int i = blockIdx.x * NTHREADS + threadIdx.x; i < n4; i += stride) {
        float4 p = p4[i];
        float4 t = t4[i];

        {
            float d = p.x - t.x;
            float lam = 2.0f * t.x - 1.0f;
            float e = (d <= 0.0f) ? lam : -lam;
            acc += fabsf(d) * __expf(e);
        }
        {
            float d = p.y - t.y;
            float lam = 2.0f * t.y - 1.0f;
            float e = (d <= 0.0f) ? lam : -lam;
            acc += fabsf(d) * __expf(e);
        }
        {
            float d = p.z - t.z;
            float lam = 2.0f * t.z - 1.0f;
            float e = (d <= 0.0f) ? lam : -lam;
            acc += fabsf(d) * __expf(e);
        }
        {
            float d = p.w - t.w;
            float lam = 2.0f * t.w - 1.0f;
            float e = (d <= 0.0f) ? lam : -lam;
            acc += fabsf(d) * __expf(e);
        }
    }

    // Warp reduction
    #pragma unroll
    for (int off = 16; off > 0; off >>= 1)
        acc += __shfl_xor_sync(0xFFFFFFFF, acc, off);

    // Block reduction via shared
    __shared__ float warp_sums[NTHREADS / 32];
    int lane = threadIdx.x & 31;
    int wid  = threadIdx.x >> 5;
    if (lane == 0) warp_sums[wid] = acc;
    __syncthreads();

    if (wid == 0) {
        float v = (lane < (NTHREADS / 32)) ? warp_sums[lane] : 0.0f;
        #pragma unroll
        for (int off = 4; off > 0; off >>= 1)
            v += __shfl_xor_sync(0xFFFFFFFF, v, off);
        if (lane == 0)
            atomicAdd(out, v * inv_n);
    }
}

extern "C" void kernel_launch(void* const* d_in, const int* in_sizes, int n_in,
                              void* d_out, int out_size) {
    const float* y_pred = (const float*)d_in[0];
    const float* y_true = (const float*)d_in[1];
    float* out = (float*)d_out;

    int n = in_sizes[0];          // 33554432, divisible by 4
    int n4 = n >> 2;
    float inv_n = 1.0f / (float)n;

    // Zero the scalar accumulator (memset node, graph-capturable).
    cudaMemsetAsync(out, 0, sizeof(float));

    skewed_loss_kernel<<<NBLOCKS, NTHREADS>>>(y_pred, y_true, out, n4, inv_n);
}

// round 15
// speedup vs baseline: 1.0478x; 1.0169x over previous
#include <cuda_runtime.h>
#include <cuda_bf16.h>

// Skewed L1 loss mean reduction — converged configuration (best measured e2e).
// lam(y) with LIM=(0,1), MEDIAN=0.5, LMAX=1 simplifies to 2y-1 on both branches.
// term = |p - t| * exp(sign(t - p) * (2t - 1));  output = mean(term).
//
// HBM-bound: 256 MiB read once, ~6.4 TB/s achieved = LTS/HBM practical
// ceiling. Minimal mainloop (lowest reg pressure measured), per-block
// atomicAdd of the scaled partial directly into out[0] overlapped with other
// blocks still streaming (no serial tail), out zeroed by a tiny kernel node.

__global__ void zero_out_kernel(float* out) {
    out[0] = 0.0f;
}

__global__ __launch_bounds__(256) void skewed_loss_kernel(
    const float* __restrict__ y_pred,
    const float* __restrict__ y_true,
    float* __restrict__ out,
    int n4,          // number of float4 chunks
    float inv_n)
{
    const float4* p4 = reinterpret_cast<const float4*>(y_pred);
    const float4* t4 = reinterpret_cast<const float4*>(y_true);

    float acc = 0.0f;
    int stride = gridDim.x * blockDim.x;
    for (int i = blockIdx.x * blockDim.x + threadIdx.x; i < n4; i += stride) {
        float4 p = p4[i];
        float4 t = t4[i];

        {
            float d = p.x - t.x;
            float lam = 2.0f * t.x - 1.0f;
            float e = (d <= 0.0f) ? lam : -lam;
            acc += fabsf(d) * __expf(e);
        }
        {
            float d = p.y - t.y;
            float lam = 2.0f * t.y - 1.0f;
            float e = (d <= 0.0f) ? lam : -lam;
            acc += fabsf(d) * __expf(e);
        }
        {
            float d = p.z - t.z;
            float lam = 2.0f * t.z - 1.0f;
            float e = (d <= 0.0f) ? lam : -lam;
            acc += fabsf(d) * __expf(e);
        }
        {
            float d = p.w - t.w;
            float lam = 2.0f * t.w - 1.0f;
            float e = (d <= 0.0f) ? lam : -lam;
            acc += fabsf(d) * __expf(e);
        }
    }

    // Warp reduction
    #pragma unroll
    for (int off = 16; off > 0; off >>= 1)
        acc += __shfl_xor_sync(0xFFFFFFFF, acc, off);

    // Block reduction via shared
    __shared__ float warp_sums[8];
    int lane = threadIdx.x & 31;
    int wid = threadIdx.x >> 5;
    if (lane == 0) warp_sums[wid] = acc;
    __syncthreads();

    if (wid == 0) {
        float v = (lane < 8) ? warp_sums[lane] : 0.0f;
        #pragma unroll
        for (int off = 4; off > 0; off >>= 1)
            v += __shfl_xor_sync(0xFFFFFFFF, v, off);
        if (lane == 0)
            atomicAdd(out, v * inv_n);
    }
}

extern "C" void kernel_launch(void* const* d_in, const int* in_sizes, int n_in,
                              void* d_out, int out_size) {
    const float* y_pred = (const float*)d_in[0];
    const float* y_true = (const float*)d_in[1];
    float* out = (float*)d_out;

    int n = in_sizes[0];          // 33554432, divisible by 4
    int n4 = n >> 2;

    zero_out_kernel<<<1, 1>>>(out);

    const int threads = 256;
    const int blocks = 148 * 8;   // 8 blocks per SM, full-chip occupancy
    float inv_n = 1.0f / (float)n;
    skewed_loss_kernel<<<blocks, threads>>>(y_pred, y_true, out, n4, inv_n);
}